// round 1
// baseline (speedup 1.0000x reference)
#include <cuda_runtime.h>
#include <cuda_bf16.h>
#include <math.h>

// Problem constants
#define T_SEQ 2048
#define NH 16
#define HD 64
#define CEMB 1024
#define KVW 512   // 8 m * 8 p * 8 q

// ---------------- scratch (device globals; no allocation allowed) -----------
static __device__ float g_qraw[T_SEQ * CEMB];
static __device__ float g_kraw[T_SEQ * CEMB];
static __device__ float g_vraw[T_SEQ * CEMB];
static __device__ float g_qn[NH * T_SEQ * HD];
static __device__ float g_kn[NH * T_SEQ * HD];
static __device__ float g_kv[NH * T_SEQ * KVW];
static __device__ float g_sc[(size_t)NH * T_SEQ * T_SEQ];
static __device__ float g_z[NH * T_SEQ * KVW];
static __device__ float g_y[T_SEQ * CEMB];

// ---------------- SGEMM config ----------------------------------------------
#define BM 128
#define BN 128
#define BK 8
#define TM 8
#define TN 8
// 256 threads per block

// C[M,N] = A[M,K] * B[N,K]^T   (both A,B row-major with K contiguous)
// If causal != 0: skip tiles strictly above the diagonal (n0 > m0).
__global__ __launch_bounds__(256) void sgemm_nt(
    const float* __restrict__ A, const float* __restrict__ B, float* __restrict__ C,
    int M, int N, int K,
    long strideA, long strideB, long strideC, int causal)
{
    int h = blockIdx.z;
    A += (long)h * strideA;
    B += (long)h * strideB;
    C += (long)h * strideC;
    int m0 = blockIdx.y * BM, n0 = blockIdx.x * BN;
    if (causal && n0 > m0) return;

    __shared__ float As[BK][BM + 4];
    __shared__ float Bs[BK][BN + 4];

    int tid = threadIdx.x;
    int tx = tid % 16, ty = tid / 16;
    int lr = tid >> 1;            // 0..127
    int lc = (tid & 1) * 4;       // 0 or 4

    float acc[TM][TN];
#pragma unroll
    for (int i = 0; i < TM; i++)
#pragma unroll
        for (int j = 0; j < TN; j++) acc[i][j] = 0.f;

    for (int k0 = 0; k0 < K; k0 += BK) {
        float4 a4 = *(const float4*)(A + (long)(m0 + lr) * K + k0 + lc);
        float4 b4 = *(const float4*)(B + (long)(n0 + lr) * K + k0 + lc);
        As[lc + 0][lr] = a4.x; As[lc + 1][lr] = a4.y;
        As[lc + 2][lr] = a4.z; As[lc + 3][lr] = a4.w;
        Bs[lc + 0][lr] = b4.x; Bs[lc + 1][lr] = b4.y;
        Bs[lc + 2][lr] = b4.z; Bs[lc + 3][lr] = b4.w;
        __syncthreads();
#pragma unroll
        for (int k = 0; k < BK; k++) {
            float ra[TM], rb[TN];
            float4 a0 = *(const float4*)&As[k][ty * TM];
            float4 a1 = *(const float4*)&As[k][ty * TM + 4];
            float4 b0 = *(const float4*)&Bs[k][tx * TN];
            float4 b1 = *(const float4*)&Bs[k][tx * TN + 4];
            ra[0]=a0.x; ra[1]=a0.y; ra[2]=a0.z; ra[3]=a0.w;
            ra[4]=a1.x; ra[5]=a1.y; ra[6]=a1.z; ra[7]=a1.w;
            rb[0]=b0.x; rb[1]=b0.y; rb[2]=b0.z; rb[3]=b0.w;
            rb[4]=b1.x; rb[5]=b1.y; rb[6]=b1.z; rb[7]=b1.w;
#pragma unroll
            for (int i = 0; i < TM; i++)
#pragma unroll
                for (int j = 0; j < TN; j++) acc[i][j] += ra[i] * rb[j];
        }
        __syncthreads();
    }
#pragma unroll
    for (int i = 0; i < TM; i++) {
        long coff = (long)(m0 + ty * TM + i) * N + n0 + tx * TN;
        float4 v0 = make_float4(acc[i][0], acc[i][1], acc[i][2], acc[i][3]);
        float4 v1 = make_float4(acc[i][4], acc[i][5], acc[i][6], acc[i][7]);
        *(float4*)(C + coff)     = v0;
        *(float4*)(C + coff + 4) = v1;
    }
}

// C[M,N] = A[M,K] * B[K,N]  (row-major), with causal K truncation:
// K loop stops at m0 + BM (probs[i,j]=0 for j>i, zero-padded to tile boundary).
__global__ __launch_bounds__(256) void sgemm_nn_causal(
    const float* __restrict__ A, const float* __restrict__ B, float* __restrict__ C,
    int M, int N, int Kfull,
    long strideA, long strideB, long strideC)
{
    int h = blockIdx.z;
    A += (long)h * strideA;
    B += (long)h * strideB;
    C += (long)h * strideC;
    int m0 = blockIdx.y * BM, n0 = blockIdx.x * BN;
    int Kend = min(Kfull, m0 + BM);

    __shared__ float As[BK][BM + 4];
    __shared__ float Bs[BK][BN + 4];

    int tid = threadIdx.x;
    int tx = tid % 16, ty = tid / 16;
    int lr = tid >> 1;            // A: 0..127
    int lc = (tid & 1) * 4;
    int br = tid >> 5;            // B: 0..7
    int bc = (tid & 31) * 4;      // 0..124

    float acc[TM][TN];
#pragma unroll
    for (int i = 0; i < TM; i++)
#pragma unroll
        for (int j = 0; j < TN; j++) acc[i][j] = 0.f;

    for (int k0 = 0; k0 < Kend; k0 += BK) {
        float4 a4 = *(const float4*)(A + (long)(m0 + lr) * Kfull + k0 + lc);
        As[lc + 0][lr] = a4.x; As[lc + 1][lr] = a4.y;
        As[lc + 2][lr] = a4.z; As[lc + 3][lr] = a4.w;
        float4 b4 = *(const float4*)(B + (long)(k0 + br) * N + n0 + bc);
        *(float4*)&Bs[br][bc] = b4;
        __syncthreads();
#pragma unroll
        for (int k = 0; k < BK; k++) {
            float ra[TM], rb[TN];
            float4 a0 = *(const float4*)&As[k][ty * TM];
            float4 a1 = *(const float4*)&As[k][ty * TM + 4];
            float4 b0 = *(const float4*)&Bs[k][tx * TN];
            float4 b1 = *(const float4*)&Bs[k][tx * TN + 4];
            ra[0]=a0.x; ra[1]=a0.y; ra[2]=a0.z; ra[3]=a0.w;
            ra[4]=a1.x; ra[5]=a1.y; ra[6]=a1.z; ra[7]=a1.w;
            rb[0]=b0.x; rb[1]=b0.y; rb[2]=b0.z; rb[3]=b0.w;
            rb[4]=b1.x; rb[5]=b1.y; rb[6]=b1.z; rb[7]=b1.w;
#pragma unroll
            for (int i = 0; i < TM; i++)
#pragma unroll
                for (int j = 0; j < TN; j++) acc[i][j] += ra[i] * rb[j];
        }
        __syncthreads();
    }
#pragma unroll
    for (int i = 0; i < TM; i++) {
        long coff = (long)(m0 + ty * TM + i) * N + n0 + tx * TN;
        float4 v0 = make_float4(acc[i][0], acc[i][1], acc[i][2], acc[i][3]);
        float4 v1 = make_float4(acc[i][4], acc[i][5], acc[i][6], acc[i][7]);
        *(float4*)(C + coff)     = v0;
        *(float4*)(C + coff + 4) = v1;
    }
}

// ---------------- rotary + RMS norm + octet norm + KV outer product ---------
// grid (NH, T), block 64 (one thread per head-dim element)
__global__ __launch_bounds__(64) void prep_kernel(
    const float* __restrict__ qraw, const float* __restrict__ kraw,
    const float* __restrict__ vraw,
    const float* __restrict__ cosp, const float* __restrict__ sinp,
    float* __restrict__ qn, float* __restrict__ kn, float* __restrict__ kv)
{
    int h = blockIdx.x, t = blockIdx.y, d = threadIdx.x;
    __shared__ float r1[64], r2[64], skc[64], sv[64];

    long base = (long)t * CEMB + h * HD;
    int j = d & 31;
    float c = cosp[t * 32 + j], s = sinp[t * 32 + j];

    float x1q = qraw[base + j], x2q = qraw[base + j + 32];
    float qv = (d < 32) ? (x1q * c + x2q * s) : (x2q * c - x1q * s);
    float x1k = kraw[base + j], x2k = kraw[base + j + 32];
    float kvv = (d < 32) ? (x1k * c + x2k * s) : (x2k * c - x1k * s);

    r1[d] = qv * qv;
    r2[d] = kvv * kvv;
    __syncthreads();
#pragma unroll
    for (int off = 32; off > 0; off >>= 1) {
        if (d < off) { r1[d] += r1[d + off]; r2[d] += r2[d + off]; }
        __syncthreads();
    }
    float rq = rsqrtf(r1[0] * (1.f / 64.f) + 1e-6f);
    float rk = rsqrtf(r2[0] * (1.f / 64.f) + 1e-6f);
    float qno = qv * rq, kno = kvv * rk;

    long nbase = ((long)h * T_SEQ + t) * HD + d;
    qn[nbase] = qno;
    kn[nbase] = kno;

    // octet (8-group) L2 norm of kn, then conjugate sign
    float o = kno * kno;
    o += __shfl_xor_sync(0xffffffffu, o, 1);
    o += __shfl_xor_sync(0xffffffffu, o, 2);
    o += __shfl_xor_sync(0xffffffffu, o, 4);
    float ko = kno / fmaxf(sqrtf(o), 1e-12f);
    skc[d] = ((d & 7) == 0) ? ko : -ko;   // oconj: keep e0, negate e1..e7
    sv[d] = vraw[base + d];
    __syncthreads();

    // KV[j, m*64 + p*8 + q] = kc[m*8+p] * v[m*8+q];  d = m*8+p
    float kc = skc[d];
    int mb = d & ~7;
    float* row = kv + ((long)h * T_SEQ + t) * KVW + d * 8;
    float4 a = make_float4(kc * sv[mb + 0], kc * sv[mb + 1], kc * sv[mb + 2], kc * sv[mb + 3]);
    float4 b = make_float4(kc * sv[mb + 4], kc * sv[mb + 5], kc * sv[mb + 6], kc * sv[mb + 7]);
    *(float4*)row = a;
    *(float4*)(row + 4) = b;
}

// ---------------- causal softmax (scale 1/8 applied here) -------------------
// grid (T, NH), block 256. Also zeroes j in (i, tile boundary) so the
// causal-truncated Z GEMM can read padded tiles safely.
__global__ __launch_bounds__(256) void softmax_kernel(float* __restrict__ sc)
{
    int i = blockIdx.x, h = blockIdx.y;
    float* row = sc + ((long)h * T_SEQ + i) * T_SEQ;
    int n = i + 1;
    int tid = threadIdx.x;
    __shared__ float sm[32];

    float lmax = -1e30f;
    for (int j = tid; j < n; j += 256) lmax = fmaxf(lmax, row[j]);
#pragma unroll
    for (int o = 16; o; o >>= 1) lmax = fmaxf(lmax, __shfl_xor_sync(~0u, lmax, o));
    if ((tid & 31) == 0) sm[tid >> 5] = lmax;
    __syncthreads();
    if (tid < 8) {
        float v = sm[tid];
#pragma unroll
        for (int o = 4; o; o >>= 1) v = fmaxf(v, __shfl_xor_sync(0xffu, v, o));
        if (tid == 0) sm[0] = v;
    }
    __syncthreads();
    float mx = sm[0];
    __syncthreads();

    float lsum = 0.f;
    for (int j = tid; j < n; j += 256) lsum += __expf((row[j] - mx) * 0.125f);
#pragma unroll
    for (int o = 16; o; o >>= 1) lsum += __shfl_xor_sync(~0u, lsum, o);
    if ((tid & 31) == 0) sm[tid >> 5] = lsum;
    __syncthreads();
    if (tid < 8) {
        float v = sm[tid];
#pragma unroll
        for (int o = 4; o; o >>= 1) v += __shfl_xor_sync(0xffu, v, o);
        if (tid == 0) sm[0] = v;
    }
    __syncthreads();
    float inv = 1.f / sm[0];

    for (int j = tid; j < n; j += 256) row[j] = __expf((row[j] - mx) * 0.125f) * inv;
    int fe = ((i >> 7) + 1) << 7;  // round up to Z-GEMM BM=128 tile boundary
    for (int j = n + tid; j < fe; j += 256) row[j] = 0.f;
}

// ---------------- octonion epilogue ------------------------------------------
__device__ __forceinline__ void qmul4(const float* q1, const float* q2, float* r)
{
    r[0] = q1[0]*q2[0] - q1[1]*q2[1] - q1[2]*q2[2] - q1[3]*q2[3];
    r[1] = q1[0]*q2[1] + q1[1]*q2[0] + q1[2]*q2[3] - q1[3]*q2[2];
    r[2] = q1[0]*q2[2] - q1[1]*q2[3] + q1[2]*q2[0] + q1[3]*q2[1];
    r[3] = q1[0]*q2[3] + q1[1]*q2[2] - q1[2]*q2[1] + q1[3]*q2[0];
}
__device__ __forceinline__ void omul8(const float* o1, const float* o2, float* r)
{
    const float* a = o1; const float* b = o1 + 4;
    const float* c = o2; const float* d = o2 + 4;
    float dc[4] = { d[0], -d[1], -d[2], -d[3] };
    float cc[4] = { c[0], -c[1], -c[2], -c[3] };
    float t1[4], t2[4];
    qmul4(a, c, t1); qmul4(dc, b, t2);
    r[0] = t1[0] - t2[0]; r[1] = t1[1] - t2[1];
    r[2] = t1[2] - t2[2]; r[3] = t1[3] - t2[3];
    qmul4(d, a, t1); qmul4(b, cc, t2);
    r[4] = t1[0] + t2[0]; r[5] = t1[1] + t2[1];
    r[6] = t1[2] + t2[2]; r[7] = t1[3] + t2[3];
}

// y[t, h*64 + m*8 + k] = sum_p ((q_im ∘ e_p) ∘ z_p)_k,  z_p[q] = Z[i,m,p,q]
__global__ __launch_bounds__(256) void epilogue_kernel(
    const float* __restrict__ qn, const float* __restrict__ Z, float* __restrict__ y)
{
    int idx = blockIdx.x * blockDim.x + threadIdx.x;  // (h*T + t)*8 + m
    int m = idx & 7;
    int ht = idx >> 3;
    int t = ht & (T_SEQ - 1);
    int h = ht >> 11;

    const float* q = qn + (long)ht * HD + m * 8;
    const float* z = Z + (long)ht * KVW + m * 64;

    float q8[8];
#pragma unroll
    for (int r = 0; r < 8; r++) q8[r] = q[r];
    float acc[8] = {0, 0, 0, 0, 0, 0, 0, 0};

#pragma unroll
    for (int p = 0; p < 8; p++) {
        float e[8] = {0, 0, 0, 0, 0, 0, 0, 0};
        e[p] = 1.f;
        float u[8], z8[8], w[8];
        omul8(q8, e, u);   // folds to signed permutation at compile time
        float4 z0 = *(const float4*)(z + p * 8);
        float4 z1 = *(const float4*)(z + p * 8 + 4);
        z8[0]=z0.x; z8[1]=z0.y; z8[2]=z0.z; z8[3]=z0.w;
        z8[4]=z1.x; z8[5]=z1.y; z8[6]=z1.z; z8[7]=z1.w;
        omul8(u, z8, w);
#pragma unroll
        for (int k = 0; k < 8; k++) acc[k] += w[k];
    }

    float* yo = y + (long)t * CEMB + h * HD + m * 8;
    float4 v0 = make_float4(acc[0], acc[1], acc[2], acc[3]);
    float4 v1 = make_float4(acc[4], acc[5], acc[6], acc[7]);
    *(float4*)yo = v0;
    *(float4*)(yo + 4) = v1;
}

// ---------------- launch -----------------------------------------------------
extern "C" void kernel_launch(void* const* d_in, const int* in_sizes, int n_in,
                              void* d_out, int out_size)
{
    const float* x    = (const float*)d_in[0];
    const float* cosp = (const float*)d_in[1];
    const float* sinp = (const float*)d_in[2];
    const float* Wq   = (const float*)d_in[3];
    const float* Wk   = (const float*)d_in[4];
    const float* Wv   = (const float*)d_in[5];
    const float* Wo   = (const float*)d_in[6];
    float* out = (float*)d_out;

    float *qraw, *kraw, *vraw, *qn, *kn, *kv, *sc, *z, *y;
    cudaGetSymbolAddress((void**)&qraw, g_qraw);
    cudaGetSymbolAddress((void**)&kraw, g_kraw);
    cudaGetSymbolAddress((void**)&vraw, g_vraw);
    cudaGetSymbolAddress((void**)&qn,   g_qn);
    cudaGetSymbolAddress((void**)&kn,   g_kn);
    cudaGetSymbolAddress((void**)&kv,   g_kv);
    cudaGetSymbolAddress((void**)&sc,   g_sc);
    cudaGetSymbolAddress((void**)&z,    g_z);
    cudaGetSymbolAddress((void**)&y,    g_y);

    dim3 blk(256);

    // 1) QKV projections: (2048x1024) @ (1024x1024)^T, NT
    sgemm_nt<<<dim3(CEMB / BN, T_SEQ / BM, 1), blk>>>(x, Wq, qraw, T_SEQ, CEMB, CEMB, 0, 0, 0, 0);
    sgemm_nt<<<dim3(CEMB / BN, T_SEQ / BM, 1), blk>>>(x, Wk, kraw, T_SEQ, CEMB, CEMB, 0, 0, 0, 0);
    sgemm_nt<<<dim3(CEMB / BN, T_SEQ / BM, 1), blk>>>(x, Wv, vraw, T_SEQ, CEMB, CEMB, 0, 0, 0, 0);

    // 2) rotary + rms + octet-norm + KV outer products
    prep_kernel<<<dim3(NH, T_SEQ), 64>>>(qraw, kraw, vraw, cosp, sinp, qn, kn, kv);

    // 3) scores = q_n @ k_n^T per head (causal tile skip)
    sgemm_nt<<<dim3(T_SEQ / BN, T_SEQ / BM, NH), blk>>>(
        qn, kn, sc, T_SEQ, T_SEQ, HD,
        (long)T_SEQ * HD, (long)T_SEQ * HD, (long)T_SEQ * T_SEQ, 1);

    // 4) causal softmax (also zero-pads to tile boundary)
    softmax_kernel<<<dim3(T_SEQ, NH), blk>>>(sc);

    // 5) Z = probs @ KV per head (causal K truncation)
    sgemm_nn_causal<<<dim3(KVW / BN, T_SEQ / BM, NH), blk>>>(
        sc, kv, z, T_SEQ, KVW, T_SEQ,
        (long)T_SEQ * T_SEQ, (long)T_SEQ * KVW, (long)T_SEQ * KVW);

    // 6) octonion epilogue -> y (2048 x 1024)
    epilogue_kernel<<<(NH * T_SEQ * 8) / 256, blk>>>(qn, z, y);

    // 7) out = y @ Wo^T
    sgemm_nt<<<dim3(CEMB / BN, T_SEQ / BM, 1), blk>>>(y, Wo, out, T_SEQ, CEMB, CEMB, 0, 0, 0, 0);
}

// round 3
// speedup vs baseline: 1.6368x; 1.6368x over previous
#include <cuda_runtime.h>
#include <cstdint>
#include <math.h>

#define T_SEQ 2048
#define NH 16
#define HD 64
#define CEMB 1024
#define KVW 512

// ---------------- scratch (device globals) ----------------------------------
static __device__ float g_qraw[T_SEQ * CEMB];
static __device__ float g_kraw[T_SEQ * CEMB];
static __device__ float g_vraw[T_SEQ * CEMB];
static __device__ float g_qn[NH * T_SEQ * HD];
static __device__ float g_kn[NH * T_SEQ * HD];
static __device__ float g_kv[NH * T_SEQ * KVW];          // [h][t][n]  (K,N layout)
static __device__ float g_sc[(size_t)NH * T_SEQ * T_SEQ];
static __device__ float g_z[NH * T_SEQ * KVW];
static __device__ float g_y[T_SEQ * CEMB];

// ---------------- helpers ----------------------------------------------------
static __device__ __forceinline__ float tf32r(float x) {
    float y; asm("cvt.rna.tf32.f32 %0, %1;" : "=f"(y) : "f"(x)); return y;
}
static __device__ __forceinline__ float4 tf32x4(float4 v) {
    return make_float4(tf32r(v.x), tf32r(v.y), tf32r(v.z), tf32r(v.w));
}
static __device__ __forceinline__ float4 sub4(float4 a, float4 b) {
    return make_float4(tf32r(a.x - b.x), tf32r(a.y - b.y),
                       tf32r(a.z - b.z), tf32r(a.w - b.w));
}
static __device__ __forceinline__ void mma_tf32(
    float* acc, uint32_t a0, uint32_t a1, uint32_t a2, uint32_t a3,
    uint32_t b0, uint32_t b1)
{
    asm volatile(
        "mma.sync.aligned.m16n8k8.row.col.f32.tf32.tf32.f32 "
        "{%0,%1,%2,%3},{%4,%5,%6,%7},{%8,%9},{%0,%1,%2,%3};"
        : "+f"(acc[0]), "+f"(acc[1]), "+f"(acc[2]), "+f"(acc[3])
        : "r"(a0), "r"(a1), "r"(a2), "r"(a3), "r"(b0), "r"(b1));
}

// ---------------- mma.sync tf32 GEMM ------------------------------------------
// C[M,N] = A[M,K] @ op(B).  BKN=0: B is [N,K] K-major (NT).  BKN=1: B is [K,N] (NN).
// SPLIT=1: 3xTF32 hi/lo split (~fp32 accuracy). Tiles: BM=BN=128, BK=16.
#define TSTR 20                 // smem row stride in floats (pad 4)
#define TILE_F (128 * TSTR)     // 2560 floats = 10240 bytes per tile

template<bool SPLIT, bool BKN>
__global__ void __launch_bounds__(256, 1) mma_gemm(
    const float* __restrict__ A, const float* __restrict__ B, float* __restrict__ C,
    int K, int lda, int ldb, int ldc,
    long sA, long sB, long sC, int causal_skip, int kend_clamp)
{
    extern __shared__ __align__(16) float sm[];
    const int STAGE = (SPLIT ? 4 : 2) * TILE_F;

    int h = blockIdx.z;
    const float* Ah = A + (long)h * sA;
    const float* Bh = B + (long)h * sB;
    float* Ch = C + (long)h * sC;
    int m0 = blockIdx.y * 128, n0 = blockIdx.x * 128;
    if (causal_skip && n0 > m0) return;
    int Kend = kend_clamp ? min(K, m0 + 128) : K;
    int nch = Kend >> 4;

    int tid = threadIdx.x;
    int lane = tid & 31, wid = tid >> 5;
    int gid = lane >> 2, tig = lane & 3;
    int warp_m = wid & 3, warp_n = wid >> 2;

    // loader indexing
    int arow = tid >> 1, akc = (tid & 1) * 8;     // A (and B when NT)
    int bk = tid & 15, bn = (tid >> 4) * 8;       // B when KN (transpose)

    float acc[2][8][4];
#pragma unroll
    for (int i = 0; i < 2; i++)
#pragma unroll
        for (int j = 0; j < 8; j++)
#pragma unroll
            for (int q = 0; q < 4; q++) acc[i][j][q] = 0.f;

    float4 ra0, ra1, rb0, rb1;

    auto LOADG = [&](int k0) {
        const float* ap = Ah + (long)(m0 + arow) * lda + k0 + akc;
        ra0 = *(const float4*)ap;
        ra1 = *(const float4*)(ap + 4);
        if (!BKN) {
            const float* bp = Bh + (long)(n0 + arow) * ldb + k0 + akc;
            rb0 = *(const float4*)bp;
            rb1 = *(const float4*)(bp + 4);
        } else {
            const float* bp = Bh + (long)(k0 + bk) * ldb + n0 + bn;
            rb0 = *(const float4*)bp;
            rb1 = *(const float4*)(bp + 4);
        }
    };
    auto STORES = [&](int sb) {
        float* Ab = sm + sb;
        float* Bb = sm + sb + TILE_F;
        int ao = arow * TSTR + akc;
        float4 h0 = tf32x4(ra0), h1 = tf32x4(ra1);
        *(float4*)(Ab + ao) = h0;
        *(float4*)(Ab + ao + 4) = h1;
        if (SPLIT) {
            float* Al = sm + sb + 2 * TILE_F;
            *(float4*)(Al + ao) = sub4(ra0, h0);
            *(float4*)(Al + ao + 4) = sub4(ra1, h1);
        }
        if (!BKN) {
            float4 g0 = tf32x4(rb0), g1 = tf32x4(rb1);
            *(float4*)(Bb + ao) = g0;
            *(float4*)(Bb + ao + 4) = g1;
            if (SPLIT) {
                float* Bl = sm + sb + 3 * TILE_F;
                *(float4*)(Bl + ao) = sub4(rb0, g0);
                *(float4*)(Bl + ao + 4) = sub4(rb1, g1);
            }
        } else {
            float4 g0 = tf32x4(rb0), g1 = tf32x4(rb1);
            Bb[(bn + 0) * TSTR + bk] = g0.x;
            Bb[(bn + 1) * TSTR + bk] = g0.y;
            Bb[(bn + 2) * TSTR + bk] = g0.z;
            Bb[(bn + 3) * TSTR + bk] = g0.w;
            Bb[(bn + 4) * TSTR + bk] = g1.x;
            Bb[(bn + 5) * TSTR + bk] = g1.y;
            Bb[(bn + 6) * TSTR + bk] = g1.z;
            Bb[(bn + 7) * TSTR + bk] = g1.w;
        }
    };

    LOADG(0);
    STORES(0);
    __syncthreads();

    const int passes = SPLIT ? 3 : 1;
    for (int ch = 0; ch < nch; ch++) {
        if (ch + 1 < nch) LOADG((ch + 1) << 4);
        int sb = (ch & 1) * STAGE;

#pragma unroll
        for (int kk = 0; kk < 2; kk++) {
            int k0 = kk * 8;
#pragma unroll
            for (int p = 0; p < 3; p++) {
                if (p >= passes) break;
                const float* Abase = sm + sb + (p == 2 ? 2 * TILE_F : 0);
                const float* Bbase = sm + sb + TILE_F + (p == 1 ? 2 * TILE_F : 0);
                uint32_t af[2][4];
#pragma unroll
                for (int mt = 0; mt < 2; mt++) {
                    int r = (warp_m * 32 + mt * 16 + gid) * TSTR + k0 + tig;
                    af[mt][0] = __float_as_uint(Abase[r]);
                    af[mt][1] = __float_as_uint(Abase[r + 8 * TSTR]);
                    af[mt][2] = __float_as_uint(Abase[r + 4]);
                    af[mt][3] = __float_as_uint(Abase[r + 8 * TSTR + 4]);
                }
                uint32_t bf[8][2];
#pragma unroll
                for (int nt = 0; nt < 8; nt++) {
                    int c = (warp_n * 64 + nt * 8 + gid) * TSTR + k0 + tig;
                    bf[nt][0] = __float_as_uint(Bbase[c]);
                    bf[nt][1] = __float_as_uint(Bbase[c + 4]);
                }
#pragma unroll
                for (int mt = 0; mt < 2; mt++)
#pragma unroll
                    for (int nt = 0; nt < 8; nt++)
                        mma_tf32(acc[mt][nt], af[mt][0], af[mt][1], af[mt][2],
                                 af[mt][3], bf[nt][0], bf[nt][1]);
            }
        }
        if (ch + 1 < nch) {
            __syncthreads();
            STORES(((ch + 1) & 1) * STAGE);
            __syncthreads();
        }
    }

#pragma unroll
    for (int mt = 0; mt < 2; mt++) {
        int r0 = m0 + warp_m * 32 + mt * 16 + gid;
#pragma unroll
        for (int nt = 0; nt < 8; nt++) {
            int c = n0 + warp_n * 64 + nt * 8 + tig * 2;
            *(float2*)(Ch + (long)r0 * ldc + c) =
                make_float2(acc[mt][nt][0], acc[mt][nt][1]);
            *(float2*)(Ch + (long)(r0 + 8) * ldc + c) =
                make_float2(acc[mt][nt][2], acc[mt][nt][3]);
        }
    }
}

// ---------------- rotary + RMS norm + octet norm + KV outer product ---------
__global__ __launch_bounds__(64) void prep_kernel(
    const float* __restrict__ qraw, const float* __restrict__ kraw,
    const float* __restrict__ vraw,
    const float* __restrict__ cosp, const float* __restrict__ sinp,
    float* __restrict__ qn, float* __restrict__ kn, float* __restrict__ kv)
{
    int h = blockIdx.x, t = blockIdx.y, d = threadIdx.x;
    __shared__ float r1[64], r2[64], skc[64], sv[64];

    long base = (long)t * CEMB + h * HD;
    int j = d & 31;
    float c = cosp[t * 32 + j], s = sinp[t * 32 + j];

    float x1q = qraw[base + j], x2q = qraw[base + j + 32];
    float qv = (d < 32) ? (x1q * c + x2q * s) : (x2q * c - x1q * s);
    float x1k = kraw[base + j], x2k = kraw[base + j + 32];
    float kvv = (d < 32) ? (x1k * c + x2k * s) : (x2k * c - x1k * s);

    r1[d] = qv * qv;
    r2[d] = kvv * kvv;
    __syncthreads();
#pragma unroll
    for (int off = 32; off > 0; off >>= 1) {
        if (d < off) { r1[d] += r1[d + off]; r2[d] += r2[d + off]; }
        __syncthreads();
    }
    float rq = rsqrtf(r1[0] * (1.f / 64.f) + 1e-6f);
    float rk = rsqrtf(r2[0] * (1.f / 64.f) + 1e-6f);
    float qno = qv * rq, kno = kvv * rk;

    long nbase = ((long)h * T_SEQ + t) * HD + d;
    qn[nbase] = qno;
    kn[nbase] = kno;

    float o = kno * kno;
    o += __shfl_xor_sync(0xffffffffu, o, 1);
    o += __shfl_xor_sync(0xffffffffu, o, 2);
    o += __shfl_xor_sync(0xffffffffu, o, 4);
    float ko = kno / fmaxf(sqrtf(o), 1e-12f);
    skc[d] = ((d & 7) == 0) ? ko : -ko;
    sv[d] = vraw[base + d];
    __syncthreads();

    float kc = skc[d];
    int mb = d & ~7;
    float* row = kv + ((long)h * T_SEQ + t) * KVW + d * 8;
    float4 a = make_float4(kc * sv[mb + 0], kc * sv[mb + 1], kc * sv[mb + 2], kc * sv[mb + 3]);
    float4 b = make_float4(kc * sv[mb + 4], kc * sv[mb + 5], kc * sv[mb + 6], kc * sv[mb + 7]);
    *(float4*)row = a;
    *(float4*)(row + 4) = b;
}

// ---------------- causal softmax ---------------------------------------------
__global__ __launch_bounds__(256) void softmax_kernel(float* __restrict__ sc)
{
    int i = blockIdx.x, h = blockIdx.y;
    float* row = sc + ((long)h * T_SEQ + i) * T_SEQ;
    int n = i + 1;
    int tid = threadIdx.x;
    __shared__ float sm[32];

    float lmax = -1e30f;
    for (int j = tid; j < n; j += 256) lmax = fmaxf(lmax, row[j]);
#pragma unroll
    for (int o = 16; o; o >>= 1) lmax = fmaxf(lmax, __shfl_xor_sync(~0u, lmax, o));
    if ((tid & 31) == 0) sm[tid >> 5] = lmax;
    __syncthreads();
    if (tid < 8) {
        float v = sm[tid];
#pragma unroll
        for (int o = 4; o; o >>= 1) v = fmaxf(v, __shfl_xor_sync(0xffu, v, o));
        if (tid == 0) sm[0] = v;
    }
    __syncthreads();
    float mx = sm[0];
    __syncthreads();

    float lsum = 0.f;
    for (int j = tid; j < n; j += 256) lsum += __expf((row[j] - mx) * 0.125f);
#pragma unroll
    for (int o = 16; o; o >>= 1) lsum += __shfl_xor_sync(~0u, lsum, o);
    if ((tid & 31) == 0) sm[tid >> 5] = lsum;
    __syncthreads();
    if (tid < 8) {
        float v = sm[tid];
#pragma unroll
        for (int o = 4; o; o >>= 1) v += __shfl_xor_sync(0xffu, v, o);
        if (tid == 0) sm[0] = v;
    }
    __syncthreads();
    float inv = 1.f / sm[0];

    for (int j = tid; j < n; j += 256) row[j] = __expf((row[j] - mx) * 0.125f) * inv;
    int fe = ((i >> 7) + 1) << 7;
    for (int j = n + tid; j < fe; j += 256) row[j] = 0.f;
}

// ---------------- octonion epilogue ------------------------------------------
__device__ __forceinline__ void qmul4(const float* q1, const float* q2, float* r)
{
    r[0] = q1[0]*q2[0] - q1[1]*q2[1] - q1[2]*q2[2] - q1[3]*q2[3];
    r[1] = q1[0]*q2[1] + q1[1]*q2[0] + q1[2]*q2[3] - q1[3]*q2[2];
    r[2] = q1[0]*q2[2] - q1[1]*q2[3] + q1[2]*q2[0] + q1[3]*q2[1];
    r[3] = q1[0]*q2[3] + q1[1]*q2[2] - q1[2]*q2[1] + q1[3]*q2[0];
}
__device__ __forceinline__ void omul8(const float* o1, const float* o2, float* r)
{
    const float* a = o1; const float* b = o1 + 4;
    const float* c = o2; const float* d = o2 + 4;
    float dc[4] = { d[0], -d[1], -d[2], -d[3] };
    float cc[4] = { c[0], -c[1], -c[2], -c[3] };
    float t1[4], t2[4];
    qmul4(a, c, t1); qmul4(dc, b, t2);
    r[0] = t1[0] - t2[0]; r[1] = t1[1] - t2[1];
    r[2] = t1[2] - t2[2]; r[3] = t1[3] - t2[3];
    qmul4(d, a, t1); qmul4(b, cc, t2);
    r[4] = t1[0] + t2[0]; r[5] = t1[1] + t2[1];
    r[6] = t1[2] + t2[2]; r[7] = t1[3] + t2[3];
}

__global__ __launch_bounds__(256) void epilogue_kernel(
    const float* __restrict__ qn, const float* __restrict__ Z, float* __restrict__ y)
{
    int idx = blockIdx.x * blockDim.x + threadIdx.x;
    int m = idx & 7;
    int ht = idx >> 3;
    int t = ht & (T_SEQ - 1);
    int h = ht >> 11;

    const float* q = qn + (long)ht * HD + m * 8;
    const float* z = Z + (long)ht * KVW + m * 64;

    float q8[8];
#pragma unroll
    for (int r = 0; r < 8; r++) q8[r] = q[r];
    float acc[8] = {0, 0, 0, 0, 0, 0, 0, 0};

#pragma unroll
    for (int p = 0; p < 8; p++) {
        float e[8] = {0, 0, 0, 0, 0, 0, 0, 0};
        e[p] = 1.f;
        float u[8], z8[8], w[8];
        omul8(q8, e, u);
        float4 z0 = *(const float4*)(z + p * 8);
        float4 z1 = *(const float4*)(z + p * 8 + 4);
        z8[0]=z0.x; z8[1]=z0.y; z8[2]=z0.z; z8[3]=z0.w;
        z8[4]=z1.x; z8[5]=z1.y; z8[6]=z1.z; z8[7]=z1.w;
        omul8(u, z8, w);
#pragma unroll
        for (int k = 0; k < 8; k++) acc[k] += w[k];
    }

    float* yo = y + (long)t * CEMB + h * HD + m * 8;
    *(float4*)yo = make_float4(acc[0], acc[1], acc[2], acc[3]);
    *(float4*)(yo + 4) = make_float4(acc[4], acc[5], acc[6], acc[7]);
}

// ---------------- launch -----------------------------------------------------
extern "C" void kernel_launch(void* const* d_in, const int* in_sizes, int n_in,
                              void* d_out, int out_size)
{
    const float* x    = (const float*)d_in[0];
    const float* cosp = (const float*)d_in[1];
    const float* sinp = (const float*)d_in[2];
    const float* Wq   = (const float*)d_in[3];
    const float* Wk   = (const float*)d_in[4];
    const float* Wv   = (const float*)d_in[5];
    const float* Wo   = (const float*)d_in[6];
    float* out = (float*)d_out;

    float *qraw, *kraw, *vraw, *qn, *kn, *kv, *sc, *z, *y;
    cudaGetSymbolAddress((void**)&qraw, g_qraw);
    cudaGetSymbolAddress((void**)&kraw, g_kraw);
    cudaGetSymbolAddress((void**)&vraw, g_vraw);
    cudaGetSymbolAddress((void**)&qn,   g_qn);
    cudaGetSymbolAddress((void**)&kn,   g_kn);
    cudaGetSymbolAddress((void**)&kv,   g_kv);
    cudaGetSymbolAddress((void**)&sc,   g_sc);
    cudaGetSymbolAddress((void**)&z,    g_z);
    cudaGetSymbolAddress((void**)&y,    g_y);

    const int smem_split = 2 * 4 * TILE_F * 4;   // 81920 B
    const int smem_1x    = 2 * 2 * TILE_F * 4;   // 40960 B
    cudaFuncSetAttribute(mma_gemm<true, false>,
                         cudaFuncAttributeMaxDynamicSharedMemorySize, smem_split);
    cudaFuncSetAttribute(mma_gemm<false, true>,
                         cudaFuncAttributeMaxDynamicSharedMemorySize, smem_1x);

    // 1) QKV projections (3xTF32 split, NT)
    mma_gemm<true, false><<<dim3(CEMB / 128, T_SEQ / 128, 1), 256, smem_split>>>(
        x, Wq, qraw, CEMB, CEMB, CEMB, CEMB, 0, 0, 0, 0, 0);
    mma_gemm<true, false><<<dim3(CEMB / 128, T_SEQ / 128, 1), 256, smem_split>>>(
        x, Wk, kraw, CEMB, CEMB, CEMB, CEMB, 0, 0, 0, 0, 0);
    mma_gemm<true, false><<<dim3(CEMB / 128, T_SEQ / 128, 1), 256, smem_split>>>(
        x, Wv, vraw, CEMB, CEMB, CEMB, CEMB, 0, 0, 0, 0, 0);

    // 2) rotary + rms + octet-norm + KV outer products
    prep_kernel<<<dim3(NH, T_SEQ), 64>>>(qraw, kraw, vraw, cosp, sinp, qn, kn, kv);

    // 3) scores = q @ k^T per head (3xTF32, causal tile skip)
    mma_gemm<true, false><<<dim3(T_SEQ / 128, T_SEQ / 128, NH), 256, smem_split>>>(
        qn, kn, sc, HD, HD, HD, T_SEQ,
        (long)T_SEQ * HD, (long)T_SEQ * HD, (long)T_SEQ * T_SEQ, 1, 0);

    // 4) causal softmax (zero-pads to 128 tile boundary)
    softmax_kernel<<<dim3(T_SEQ, NH), 256>>>(sc);

    // 5) Z = probs @ KV per head (1xTF32-rna, B in [K,N] layout, causal K clamp)
    mma_gemm<false, true><<<dim3(KVW / 128, T_SEQ / 128, NH), 256, smem_1x>>>(
        sc, kv, z, T_SEQ, T_SEQ, KVW, KVW,
        (long)T_SEQ * T_SEQ, (long)T_SEQ * KVW, (long)T_SEQ * KVW, 0, 1);

    // 6) octonion epilogue -> y
    epilogue_kernel<<<(NH * T_SEQ * 8) / 256, 256>>>(qn, z, y);

    // 7) out = y @ Wo^T (3xTF32)
    mma_gemm<true, false><<<dim3(CEMB / 128, T_SEQ / 128, 1), 256, smem_split>>>(
        y, Wo, out, CEMB, CEMB, CEMB, CEMB, 0, 0, 0, 0, 0);
}

// round 4
// speedup vs baseline: 1.9783x; 1.2087x over previous
#include <cuda_runtime.h>
#include <cstdint>
#include <math.h>

#define T_SEQ 2048
#define NH 16
#define HD 64
#define CEMB 1024
#define KVW 512

// ---------------- scratch (device globals) ----------------------------------
static __device__ float g_qraw[T_SEQ * CEMB];
static __device__ float g_kraw[T_SEQ * CEMB];
static __device__ float g_vraw[T_SEQ * CEMB];
static __device__ float g_qn[NH * T_SEQ * HD];
static __device__ float g_kn[NH * T_SEQ * HD];
static __device__ float g_kv[NH * T_SEQ * KVW];          // [h][t][n]  (K,N layout)
static __device__ float g_sc[(size_t)NH * T_SEQ * T_SEQ];
static __device__ float g_z[NH * T_SEQ * KVW];
static __device__ float g_y[T_SEQ * CEMB];

// ---------------- helpers ----------------------------------------------------
static __device__ __forceinline__ float tf32r(float x) {
    float y; asm("cvt.rna.tf32.f32 %0, %1;" : "=f"(y) : "f"(x)); return y;
}
static __device__ __forceinline__ float4 tf32x4(float4 v) {
    return make_float4(tf32r(v.x), tf32r(v.y), tf32r(v.z), tf32r(v.w));
}
static __device__ __forceinline__ void mma_tf32(
    float* acc, uint32_t a0, uint32_t a1, uint32_t a2, uint32_t a3,
    uint32_t b0, uint32_t b1)
{
    asm volatile(
        "mma.sync.aligned.m16n8k8.row.col.f32.tf32.tf32.f32 "
        "{%0,%1,%2,%3},{%4,%5,%6,%7},{%8,%9},{%0,%1,%2,%3};"
        : "+f"(acc[0]), "+f"(acc[1]), "+f"(acc[2]), "+f"(acc[3])
        : "r"(a0), "r"(a1), "r"(a2), "r"(a3), "r"(b0), "r"(b1));
}
static __device__ __forceinline__ void mma_bf16(
    float* acc, uint32_t a0, uint32_t a1, uint32_t a2, uint32_t a3,
    uint32_t b0, uint32_t b1)
{
    asm volatile(
        "mma.sync.aligned.m16n8k16.row.col.f32.bf16.bf16.f32 "
        "{%0,%1,%2,%3},{%4,%5,%6,%7},{%8,%9},{%0,%1,%2,%3};"
        : "+f"(acc[0]), "+f"(acc[1]), "+f"(acc[2]), "+f"(acc[3])
        : "r"(a0), "r"(a1), "r"(a2), "r"(a3), "r"(b0), "r"(b1));
}
// pack two floats into bf16x2 hi + residual-lo pair
static __device__ __forceinline__ uint2 pack_split(float f0, float f1) {
    uint32_t h;
    asm("cvt.rn.bf16x2.f32 %0, %1, %2;" : "=r"(h) : "f"(f1), "f"(f0));
    float h0 = __uint_as_float(h << 16);
    float h1 = __uint_as_float(h & 0xffff0000u);
    uint32_t l;
    float r0 = f0 - h0, r1 = f1 - h1;
    asm("cvt.rn.bf16x2.f32 %0, %1, %2;" : "=r"(l) : "f"(r1), "f"(r0));
    return make_uint2(h, l);
}

// ================= bf16 split GEMM (NT): C = A[M,K] @ B[N,K]^T ===============
// 3 passes (hi*hi + hi*lo + lo*hi) ~ fp32 accuracy. BM=BN=128, BK=16 floats.
#define BSTR 12                  // smem row stride in uint32 (8 pairs + 4 pad)
#define BTILE_U (128 * BSTR)     // uints per tile

__global__ void __launch_bounds__(256, 2) bf16_gemm_nt(
    const float* __restrict__ A, const float* __restrict__ B, float* __restrict__ C,
    int K, int lda, int ldb, int ldc,
    long sA, long sB, long sC, int causal_skip)
{
    extern __shared__ __align__(16) uint32_t smu[];
    const int STAGE = 4 * BTILE_U;

    int h = blockIdx.z;
    const float* Ah = A + (long)h * sA;
    const float* Bh = B + (long)h * sB;
    float* Ch = C + (long)h * sC;
    int m0 = blockIdx.y * 128, n0 = blockIdx.x * 128;
    if (causal_skip && n0 > m0) return;
    int nch = K >> 4;

    int tid = threadIdx.x;
    int lane = tid & 31, wid = tid >> 5;
    int gid = lane >> 2, tig = lane & 3;
    int warp_m = wid & 3, warp_n = wid >> 2;
    int arow = tid >> 1, akc = (tid & 1) * 8;

    float acc[2][8][4];
#pragma unroll
    for (int i = 0; i < 2; i++)
#pragma unroll
        for (int j = 0; j < 8; j++)
#pragma unroll
            for (int q = 0; q < 4; q++) acc[i][j][q] = 0.f;

    float4 ra0, ra1, rb0, rb1;
    auto LOADG = [&](int k0) {
        const float* ap = Ah + (long)(m0 + arow) * lda + k0 + akc;
        ra0 = *(const float4*)ap;
        ra1 = *(const float4*)(ap + 4);
        const float* bp = Bh + (long)(n0 + arow) * ldb + k0 + akc;
        rb0 = *(const float4*)bp;
        rb1 = *(const float4*)(bp + 4);
    };
    auto STORES = [&](int sb) {
        int ao = arow * BSTR + (akc >> 1);
        uint2 p0 = pack_split(ra0.x, ra0.y), p1 = pack_split(ra0.z, ra0.w);
        uint2 p2 = pack_split(ra1.x, ra1.y), p3 = pack_split(ra1.z, ra1.w);
        *(uint4*)(smu + sb + ao)               = make_uint4(p0.x, p1.x, p2.x, p3.x);
        *(uint4*)(smu + sb + 2 * BTILE_U + ao) = make_uint4(p0.y, p1.y, p2.y, p3.y);
        uint2 q0 = pack_split(rb0.x, rb0.y), q1 = pack_split(rb0.z, rb0.w);
        uint2 q2 = pack_split(rb1.x, rb1.y), q3 = pack_split(rb1.z, rb1.w);
        *(uint4*)(smu + sb + BTILE_U + ao)     = make_uint4(q0.x, q1.x, q2.x, q3.x);
        *(uint4*)(smu + sb + 3 * BTILE_U + ao) = make_uint4(q0.y, q1.y, q2.y, q3.y);
    };

    LOADG(0);
    STORES(0);
    __syncthreads();

    for (int ch = 0; ch < nch; ch++) {
        if (ch + 1 < nch) LOADG((ch + 1) << 4);
        int sb = (ch & 1) * STAGE;
#pragma unroll
        for (int p = 0; p < 3; p++) {
            const uint32_t* Abase = smu + sb + (p == 2 ? 2 * BTILE_U : 0);
            const uint32_t* Bbase = smu + sb + BTILE_U + (p == 1 ? 2 * BTILE_U : 0);
            uint32_t af[2][4];
#pragma unroll
            for (int mt = 0; mt < 2; mt++) {
                int r = (warp_m * 32 + mt * 16 + gid) * BSTR + tig;
                af[mt][0] = Abase[r];
                af[mt][1] = Abase[r + 8 * BSTR];
                af[mt][2] = Abase[r + 4];
                af[mt][3] = Abase[r + 8 * BSTR + 4];
            }
            uint32_t bf[8][2];
#pragma unroll
            for (int nt = 0; nt < 8; nt++) {
                int c = (warp_n * 64 + nt * 8 + gid) * BSTR + tig;
                bf[nt][0] = Bbase[c];
                bf[nt][1] = Bbase[c + 4];
            }
#pragma unroll
            for (int mt = 0; mt < 2; mt++)
#pragma unroll
                for (int nt = 0; nt < 8; nt++)
                    mma_bf16(acc[mt][nt], af[mt][0], af[mt][1], af[mt][2],
                             af[mt][3], bf[nt][0], bf[nt][1]);
        }
        if (ch + 1 < nch) {
            __syncthreads();
            STORES(((ch + 1) & 1) * STAGE);
            __syncthreads();
        }
    }

#pragma unroll
    for (int mt = 0; mt < 2; mt++) {
        int r0 = m0 + warp_m * 32 + mt * 16 + gid;
#pragma unroll
        for (int nt = 0; nt < 8; nt++) {
            int c = n0 + warp_n * 64 + nt * 8 + tig * 2;
            *(float2*)(Ch + (long)r0 * ldc + c) =
                make_float2(acc[mt][nt][0], acc[mt][nt][1]);
            *(float2*)(Ch + (long)(r0 + 8) * ldc + c) =
                make_float2(acc[mt][nt][2], acc[mt][nt][3]);
        }
    }
}

// ================= tf32 1x GEMM (NN): C = A[M,K] @ B[K,N] (Z path) ==========
#define TSTR 20
#define TILE_F (128 * TSTR)

__global__ void __launch_bounds__(256, 2) tf32_gemm_nn(
    const float* __restrict__ A, const float* __restrict__ B, float* __restrict__ C,
    int K, int lda, int ldb, int ldc,
    long sA, long sB, long sC, int kend_clamp)
{
    extern __shared__ __align__(16) float sm[];
    const int STAGE = 2 * TILE_F;

    int h = blockIdx.z;
    const float* Ah = A + (long)h * sA;
    const float* Bh = B + (long)h * sB;
    float* Ch = C + (long)h * sC;
    int m0 = blockIdx.y * 128, n0 = blockIdx.x * 128;
    int Kend = kend_clamp ? min(K, m0 + 128) : K;
    int nch = Kend >> 4;

    int tid = threadIdx.x;
    int lane = tid & 31, wid = tid >> 5;
    int gid = lane >> 2, tig = lane & 3;
    int warp_m = wid & 3, warp_n = wid >> 2;
    int arow = tid >> 1, akc = (tid & 1) * 8;
    int bk = tid & 15, bn = (tid >> 4) * 8;

    float acc[2][8][4];
#pragma unroll
    for (int i = 0; i < 2; i++)
#pragma unroll
        for (int j = 0; j < 8; j++)
#pragma unroll
            for (int q = 0; q < 4; q++) acc[i][j][q] = 0.f;

    float4 ra0, ra1, rb0, rb1;
    auto LOADG = [&](int k0) {
        const float* ap = Ah + (long)(m0 + arow) * lda + k0 + akc;
        ra0 = *(const float4*)ap;
        ra1 = *(const float4*)(ap + 4);
        const float* bp = Bh + (long)(k0 + bk) * ldb + n0 + bn;
        rb0 = *(const float4*)bp;
        rb1 = *(const float4*)(bp + 4);
    };
    auto STORES = [&](int sb) {
        float* Ab = sm + sb;
        float* Bb = sm + sb + TILE_F;
        int ao = arow * TSTR + akc;
        *(float4*)(Ab + ao) = tf32x4(ra0);
        *(float4*)(Ab + ao + 4) = tf32x4(ra1);
        float4 g0 = tf32x4(rb0), g1 = tf32x4(rb1);
        Bb[(bn + 0) * TSTR + bk] = g0.x;
        Bb[(bn + 1) * TSTR + bk] = g0.y;
        Bb[(bn + 2) * TSTR + bk] = g0.z;
        Bb[(bn + 3) * TSTR + bk] = g0.w;
        Bb[(bn + 4) * TSTR + bk] = g1.x;
        Bb[(bn + 5) * TSTR + bk] = g1.y;
        Bb[(bn + 6) * TSTR + bk] = g1.z;
        Bb[(bn + 7) * TSTR + bk] = g1.w;
    };

    LOADG(0);
    STORES(0);
    __syncthreads();

    for (int ch = 0; ch < nch; ch++) {
        if (ch + 1 < nch) LOADG((ch + 1) << 4);
        int sb = (ch & 1) * STAGE;
#pragma unroll
        for (int kk = 0; kk < 2; kk++) {
            int k0 = kk * 8;
            const float* Abase = sm + sb;
            const float* Bbase = sm + sb + TILE_F;
            uint32_t af[2][4];
#pragma unroll
            for (int mt = 0; mt < 2; mt++) {
                int r = (warp_m * 32 + mt * 16 + gid) * TSTR + k0 + tig;
                af[mt][0] = __float_as_uint(Abase[r]);
                af[mt][1] = __float_as_uint(Abase[r + 8 * TSTR]);
                af[mt][2] = __float_as_uint(Abase[r + 4]);
                af[mt][3] = __float_as_uint(Abase[r + 8 * TSTR + 4]);
            }
            uint32_t bf[8][2];
#pragma unroll
            for (int nt = 0; nt < 8; nt++) {
                int c = (warp_n * 64 + nt * 8 + gid) * TSTR + k0 + tig;
                bf[nt][0] = __float_as_uint(Bbase[c]);
                bf[nt][1] = __float_as_uint(Bbase[c + 4]);
            }
#pragma unroll
            for (int mt = 0; mt < 2; mt++)
#pragma unroll
                for (int nt = 0; nt < 8; nt++)
                    mma_tf32(acc[mt][nt], af[mt][0], af[mt][1], af[mt][2],
                             af[mt][3], bf[nt][0], bf[nt][1]);
        }
        if (ch + 1 < nch) {
            __syncthreads();
            STORES(((ch + 1) & 1) * STAGE);
            __syncthreads();
        }
    }

#pragma unroll
    for (int mt = 0; mt < 2; mt++) {
        int r0 = m0 + warp_m * 32 + mt * 16 + gid;
#pragma unroll
        for (int nt = 0; nt < 8; nt++) {
            int c = n0 + warp_n * 64 + nt * 8 + tig * 2;
            *(float2*)(Ch + (long)r0 * ldc + c) =
                make_float2(acc[mt][nt][0], acc[mt][nt][1]);
            *(float2*)(Ch + (long)(r0 + 8) * ldc + c) =
                make_float2(acc[mt][nt][2], acc[mt][nt][3]);
        }
    }
}

// ---------------- rotary + RMS norm + octet norm + KV outer product ---------
__global__ __launch_bounds__(64) void prep_kernel(
    const float* __restrict__ qraw, const float* __restrict__ kraw,
    const float* __restrict__ vraw,
    const float* __restrict__ cosp, const float* __restrict__ sinp,
    float* __restrict__ qn, float* __restrict__ kn, float* __restrict__ kv)
{
    int h = blockIdx.x, t = blockIdx.y, d = threadIdx.x;
    __shared__ float r1[64], r2[64], skc[64], sv[64];

    long base = (long)t * CEMB + h * HD;
    int j = d & 31;
    float c = cosp[t * 32 + j], s = sinp[t * 32 + j];

    float x1q = qraw[base + j], x2q = qraw[base + j + 32];
    float qv = (d < 32) ? (x1q * c + x2q * s) : (x2q * c - x1q * s);
    float x1k = kraw[base + j], x2k = kraw[base + j + 32];
    float kvv = (d < 32) ? (x1k * c + x2k * s) : (x2k * c - x1k * s);

    r1[d] = qv * qv;
    r2[d] = kvv * kvv;
    __syncthreads();
#pragma unroll
    for (int off = 32; off > 0; off >>= 1) {
        if (d < off) { r1[d] += r1[d + off]; r2[d] += r2[d + off]; }
        __syncthreads();
    }
    float rq = rsqrtf(r1[0] * (1.f / 64.f) + 1e-6f);
    float rk = rsqrtf(r2[0] * (1.f / 64.f) + 1e-6f);
    float qno = qv * rq, kno = kvv * rk;

    long nbase = ((long)h * T_SEQ + t) * HD + d;
    qn[nbase] = qno;
    kn[nbase] = kno;

    float o = kno * kno;
    o += __shfl_xor_sync(0xffffffffu, o, 1);
    o += __shfl_xor_sync(0xffffffffu, o, 2);
    o += __shfl_xor_sync(0xffffffffu, o, 4);
    float ko = kno / fmaxf(sqrtf(o), 1e-12f);
    skc[d] = ((d & 7) == 0) ? ko : -ko;
    sv[d] = vraw[base + d];
    __syncthreads();

    float kc = skc[d];
    int mb = d & ~7;
    float* row = kv + ((long)h * T_SEQ + t) * KVW + d * 8;
    float4 a = make_float4(kc * sv[mb + 0], kc * sv[mb + 1], kc * sv[mb + 2], kc * sv[mb + 3]);
    float4 b = make_float4(kc * sv[mb + 4], kc * sv[mb + 5], kc * sv[mb + 6], kc * sv[mb + 7]);
    *(float4*)row = a;
    *(float4*)(row + 4) = b;
}

// ---------------- causal softmax ---------------------------------------------
__global__ __launch_bounds__(256) void softmax_kernel(float* __restrict__ sc)
{
    int i = blockIdx.x, h = blockIdx.y;
    float* row = sc + ((long)h * T_SEQ + i) * T_SEQ;
    int n = i + 1;
    int tid = threadIdx.x;
    __shared__ float sm[32];

    float lmax = -1e30f;
    for (int j = tid; j < n; j += 256) lmax = fmaxf(lmax, row[j]);
#pragma unroll
    for (int o = 16; o; o >>= 1) lmax = fmaxf(lmax, __shfl_xor_sync(~0u, lmax, o));
    if ((tid & 31) == 0) sm[tid >> 5] = lmax;
    __syncthreads();
    if (tid < 8) {
        float v = sm[tid];
#pragma unroll
        for (int o = 4; o; o >>= 1) v = fmaxf(v, __shfl_xor_sync(0xffu, v, o));
        if (tid == 0) sm[0] = v;
    }
    __syncthreads();
    float mx = sm[0];
    __syncthreads();

    float lsum = 0.f;
    for (int j = tid; j < n; j += 256) lsum += __expf((row[j] - mx) * 0.125f);
#pragma unroll
    for (int o = 16; o; o >>= 1) lsum += __shfl_xor_sync(~0u, lsum, o);
    if ((tid & 31) == 0) sm[tid >> 5] = lsum;
    __syncthreads();
    if (tid < 8) {
        float v = sm[tid];
#pragma unroll
        for (int o = 4; o; o >>= 1) v += __shfl_xor_sync(0xffu, v, o);
        if (tid == 0) sm[0] = v;
    }
    __syncthreads();
    float inv = 1.f / sm[0];

    for (int j = tid; j < n; j += 256) row[j] = __expf((row[j] - mx) * 0.125f) * inv;
    int fe = ((i >> 7) + 1) << 7;
    for (int j = n + tid; j < fe; j += 256) row[j] = 0.f;
}

// ---------------- octonion epilogue ------------------------------------------
__device__ __forceinline__ void qmul4(const float* q1, const float* q2, float* r)
{
    r[0] = q1[0]*q2[0] - q1[1]*q2[1] - q1[2]*q2[2] - q1[3]*q2[3];
    r[1] = q1[0]*q2[1] + q1[1]*q2[0] + q1[2]*q2[3] - q1[3]*q2[2];
    r[2] = q1[0]*q2[2] - q1[1]*q2[3] + q1[2]*q2[0] + q1[3]*q2[1];
    r[3] = q1[0]*q2[3] + q1[1]*q2[2] - q1[2]*q2[1] + q1[3]*q2[0];
}
__device__ __forceinline__ void omul8(const float* o1, const float* o2, float* r)
{
    const float* a = o1; const float* b = o1 + 4;
    const float* c = o2; const float* d = o2 + 4;
    float dc[4] = { d[0], -d[1], -d[2], -d[3] };
    float cc[4] = { c[0], -c[1], -c[2], -c[3] };
    float t1[4], t2[4];
    qmul4(a, c, t1); qmul4(dc, b, t2);
    r[0] = t1[0] - t2[0]; r[1] = t1[1] - t2[1];
    r[2] = t1[2] - t2[2]; r[3] = t1[3] - t2[3];
    qmul4(d, a, t1); qmul4(b, cc, t2);
    r[4] = t1[0] + t2[0]; r[5] = t1[1] + t2[1];
    r[6] = t1[2] + t2[2]; r[7] = t1[3] + t2[3];
}

__global__ __launch_bounds__(256) void epilogue_kernel(
    const float* __restrict__ qn, const float* __restrict__ Z, float* __restrict__ y)
{
    int idx = blockIdx.x * blockDim.x + threadIdx.x;
    int m = idx & 7;
    int ht = idx >> 3;
    int t = ht & (T_SEQ - 1);
    int h = ht >> 11;

    const float* q = qn + (long)ht * HD + m * 8;
    const float* z = Z + (long)ht * KVW + m * 64;

    float q8[8];
#pragma unroll
    for (int r = 0; r < 8; r++) q8[r] = q[r];
    float acc[8] = {0, 0, 0, 0, 0, 0, 0, 0};

#pragma unroll
    for (int p = 0; p < 8; p++) {
        float e[8] = {0, 0, 0, 0, 0, 0, 0, 0};
        e[p] = 1.f;
        float u[8], z8[8], w[8];
        omul8(q8, e, u);
        float4 z0 = *(const float4*)(z + p * 8);
        float4 z1 = *(const float4*)(z + p * 8 + 4);
        z8[0]=z0.x; z8[1]=z0.y; z8[2]=z0.z; z8[3]=z0.w;
        z8[4]=z1.x; z8[5]=z1.y; z8[6]=z1.z; z8[7]=z1.w;
        omul8(u, z8, w);
#pragma unroll
        for (int k = 0; k < 8; k++) acc[k] += w[k];
    }

    float* yo = y + (long)t * CEMB + h * HD + m * 8;
    *(float4*)yo = make_float4(acc[0], acc[1], acc[2], acc[3]);
    *(float4*)(yo + 4) = make_float4(acc[4], acc[5], acc[6], acc[7]);
}

// ---------------- launch -----------------------------------------------------
extern "C" void kernel_launch(void* const* d_in, const int* in_sizes, int n_in,
                              void* d_out, int out_size)
{
    const float* x    = (const float*)d_in[0];
    const float* cosp = (const float*)d_in[1];
    const float* sinp = (const float*)d_in[2];
    const float* Wq   = (const float*)d_in[3];
    const float* Wk   = (const float*)d_in[4];
    const float* Wv   = (const float*)d_in[5];
    const float* Wo   = (const float*)d_in[6];
    float* out = (float*)d_out;

    float *qraw, *kraw, *vraw, *qn, *kn, *kv, *sc, *z, *y;
    cudaGetSymbolAddress((void**)&qraw, g_qraw);
    cudaGetSymbolAddress((void**)&kraw, g_kraw);
    cudaGetSymbolAddress((void**)&vraw, g_vraw);
    cudaGetSymbolAddress((void**)&qn,   g_qn);
    cudaGetSymbolAddress((void**)&kn,   g_kn);
    cudaGetSymbolAddress((void**)&kv,   g_kv);
    cudaGetSymbolAddress((void**)&sc,   g_sc);
    cudaGetSymbolAddress((void**)&z,    g_z);
    cudaGetSymbolAddress((void**)&y,    g_y);

    const int smem_bf16 = 2 * 4 * BTILE_U * 4;   // 49152 B
    const int smem_tf32 = 2 * 2 * TILE_F * 4;    // 40960 B
    cudaFuncSetAttribute(bf16_gemm_nt,
                         cudaFuncAttributeMaxDynamicSharedMemorySize, smem_bf16);
    cudaFuncSetAttribute(tf32_gemm_nn,
                         cudaFuncAttributeMaxDynamicSharedMemorySize, smem_tf32);

    // 1) QKV projections (3xBF16 split, NT)
    bf16_gemm_nt<<<dim3(CEMB / 128, T_SEQ / 128, 1), 256, smem_bf16>>>(
        x, Wq, qraw, CEMB, CEMB, CEMB, CEMB, 0, 0, 0, 0);
    bf16_gemm_nt<<<dim3(CEMB / 128, T_SEQ / 128, 1), 256, smem_bf16>>>(
        x, Wk, kraw, CEMB, CEMB, CEMB, CEMB, 0, 0, 0, 0);
    bf16_gemm_nt<<<dim3(CEMB / 128, T_SEQ / 128, 1), 256, smem_bf16>>>(
        x, Wv, vraw, CEMB, CEMB, CEMB, CEMB, 0, 0, 0, 0);

    // 2) rotary + rms + octet-norm + KV outer products
    prep_kernel<<<dim3(NH, T_SEQ), 64>>>(qraw, kraw, vraw, cosp, sinp, qn, kn, kv);

    // 3) scores = q @ k^T per head (3xBF16 split, causal tile skip)
    bf16_gemm_nt<<<dim3(T_SEQ / 128, T_SEQ / 128, NH), 256, smem_bf16>>>(
        qn, kn, sc, HD, HD, HD, T_SEQ,
        (long)T_SEQ * HD, (long)T_SEQ * HD, (long)T_SEQ * T_SEQ, 1);

    // 4) causal softmax (zero-pads to 128 tile boundary)
    softmax_kernel<<<dim3(T_SEQ, NH), 256>>>(sc);

    // 5) Z = probs @ KV per head (1xTF32, B in [K,N] layout, causal K clamp)
    tf32_gemm_nn<<<dim3(KVW / 128, T_SEQ / 128, NH), 256, smem_tf32>>>(
        sc, kv, z, T_SEQ, T_SEQ, KVW, KVW,
        (long)T_SEQ * T_SEQ, (long)T_SEQ * KVW, (long)T_SEQ * KVW, 1);

    // 6) octonion epilogue -> y
    epilogue_kernel<<<(NH * T_SEQ * 8) / 256, 256>>>(qn, z, y);

    // 7) out = y @ Wo^T (3xBF16 split)
    bf16_gemm_nt<<<dim3(CEMB / 128, T_SEQ / 128, 1), 256, smem_bf16>>>(
        y, Wo, out, CEMB, CEMB, CEMB, CEMB, 0, 0, 0, 0);
}